// round 10
// baseline (speedup 1.0000x reference)
#include <cuda_runtime.h>
#include <math.h>
#include <stdint.h>

// Problem constants (B=1, H=16, L=1024, D=64)
#define NSEQ 16
#define LSEQ 1024
#define DIM  64
#define D2   128          // feature dim = 2*DIM
#define CHK  64           // chunk length
#define NC   (LSEQ/CHK)   // 16 chunks per sequence

// Scratch: per-(seq,chunk) RAW KV sums [D2][DIM] and k-sums [D2]
// (no prefix scan -- consumers do lookback reduction themselves)
__device__ float g_kv[NSEQ * NC * D2 * DIM];    // 8 MB
__device__ float g_ksum[NSEQ * NC * D2];        // 128 KB

// ---------------------------------------------------------------------------
// helpers
// ---------------------------------------------------------------------------
__device__ __forceinline__ float f2tf(float x) {
    uint32_t r;
    asm("cvt.rna.tf32.f32 %0, %1;" : "=r"(r) : "f"(x));
    return __uint_as_float(r);
}

__device__ __forceinline__ void mma_tf32(float d[4],
                                         const uint32_t a[4],
                                         const uint32_t b[2],
                                         const float c[4]) {
    asm volatile(
        "mma.sync.aligned.m16n8k8.row.col.f32.tf32.tf32.f32 "
        "{%0,%1,%2,%3}, {%4,%5,%6,%7}, {%8,%9}, {%10,%11,%12,%13};\n"
        : "=f"(d[0]), "=f"(d[1]), "=f"(d[2]), "=f"(d[3])
        : "r"(a[0]), "r"(a[1]), "r"(a[2]), "r"(a[3]),
          "r"(b[0]), "r"(b[1]),
          "f"(c[0]), "f"(c[1]), "f"(c[2]), "f"(c[3]));
}

#define BITS(x) __float_as_uint(x)

// ---------------------------------------------------------------------------
// Kernel 1: per-chunk KV sums via tensor cores.
// grid = NSEQ*NC = 256, 256 threads (8 warps).
// C[128(d2) x 64(dv)] = k~^T @ v over K=64 positions.
// ---------------------------------------------------------------------------
#define K1_KS 136
#define K1_VS 72
#define K1_SMEM ((CHK*K1_KS + CHK*K1_VS) * sizeof(float))

__global__ __launch_bounds__(256)
void k_chunksum(const float* __restrict__ kg_,
                const float* __restrict__ vg_) {
    extern __shared__ float sm[];
    float* ks = sm;                   // [64][136]
    float* vs = sm + CHK * K1_KS;     // [64][72]

    const int s = blockIdx.x >> 4;
    const int c = blockIdx.x & 15;
    const int t = threadIdx.x;

    const float* kg = kg_ + (size_t)(s * LSEQ + c * CHK) * DIM;
    const float* vg = vg_ + (size_t)(s * LSEQ + c * CHK) * DIM;

#pragma unroll
    for (int i = t; i < CHK * DIM / 4; i += 256) {
        int j = i >> 4;
        int d = (i & 15) * 4;
        float4 k4 = reinterpret_cast<const float4*>(kg)[i];
        float4 v4 = reinterpret_cast<const float4*>(vg)[i];
        int gl = c * CHK + j;
        float w = 1.5707963267948966f * (float)(gl + 1) * (1.0f / (float)LSEQ);
        float sw, cw;
        __sincosf(w, &sw, &cw);
        float kx = fmaxf(k4.x, 0.f), ky = fmaxf(k4.y, 0.f);
        float kz = fmaxf(k4.z, 0.f), kw = fmaxf(k4.w, 0.f);
        *reinterpret_cast<float4*>(ks + j * K1_KS + d) =
            make_float4(f2tf(kx * sw), f2tf(ky * sw), f2tf(kz * sw), f2tf(kw * sw));
        *reinterpret_cast<float4*>(ks + j * K1_KS + 64 + d) =
            make_float4(f2tf(kx * cw), f2tf(ky * cw), f2tf(kz * cw), f2tf(kw * cw));
        *reinterpret_cast<float4*>(vs + j * K1_VS + d) =
            make_float4(f2tf(v4.x), f2tf(v4.y), f2tf(v4.z), f2tf(v4.w));
    }
    __syncthreads();

    const int wid  = t >> 5;
    const int lane = t & 31;
    const int g    = lane >> 2;
    const int tig  = lane & 3;
    const int warpM = (wid >> 1) * 32;   // 0,32,64,96 (d2)
    const int warpN = (wid & 1) * 32;    // 0,32 (dv)

    float acc[2][4][4];
#pragma unroll
    for (int mt = 0; mt < 2; mt++)
#pragma unroll
        for (int nt = 0; nt < 4; nt++)
#pragma unroll
            for (int cc = 0; cc < 4; cc++) acc[mt][nt][cc] = 0.f;

#pragma unroll
    for (int kk = 0; kk < 8; kk++) {
        const int k0 = kk * 8;
        uint32_t af[2][4];
#pragma unroll
        for (int mt = 0; mt < 2; mt++) {
            int mb = warpM + mt * 16 + g;
            af[mt][0] = BITS(ks[(k0 + tig)     * K1_KS + mb]);
            af[mt][1] = BITS(ks[(k0 + tig)     * K1_KS + mb + 8]);
            af[mt][2] = BITS(ks[(k0 + tig + 4) * K1_KS + mb]);
            af[mt][3] = BITS(ks[(k0 + tig + 4) * K1_KS + mb + 8]);
        }
        uint32_t bf[4][2];
#pragma unroll
        for (int nt = 0; nt < 4; nt++) {
            int nb = warpN + nt * 8 + g;
            bf[nt][0] = BITS(vs[(k0 + tig)     * K1_VS + nb]);
            bf[nt][1] = BITS(vs[(k0 + tig + 4) * K1_VS + nb]);
        }
#pragma unroll
        for (int mt = 0; mt < 2; mt++)
#pragma unroll
            for (int nt = 0; nt < 4; nt++)
                mma_tf32(acc[mt][nt], af[mt], bf[nt], acc[mt][nt]);
    }

    // Store chunk KV sum straight to L2 (no L1 reuse).
    float* outp = g_kv + (size_t)(s * NC + c) * D2 * DIM;
#pragma unroll
    for (int mt = 0; mt < 2; mt++)
#pragma unroll
        for (int nt = 0; nt < 4; nt++) {
            int m0 = warpM + mt * 16 + g;
            int n0 = warpN + nt * 8 + 2 * tig;
            __stcg((float2*)(outp + m0 * DIM + n0),
                   make_float2(acc[mt][nt][0], acc[mt][nt][1]));
            __stcg((float2*)(outp + (m0 + 8) * DIM + n0),
                   make_float2(acc[mt][nt][2], acc[mt][nt][3]));
        }

    // k-sum per feature dim.
    if (t < D2) {
        float ssum = 0.f;
#pragma unroll 8
        for (int j = 0; j < CHK; j++) ssum += ks[j * K1_KS + t];
        __stcg(&g_ksum[(size_t)(s * NC + c) * D2 + t], ssum);
    }
}

// ---------------------------------------------------------------------------
// Kernel 2 (= old kernel 3 + inlined lookback): per-chunk output.
// grid = NSEQ*NC, 256 threads.
// S0 = sum of raw chunk partials i<c, reduced in registers (no scan kernel).
// ---------------------------------------------------------------------------
#define QS3 132
#define US3 132
#define S0S 72
#define VS3 72
#define AS3 68
#define K3_U_FLOATS 9216   /* max(64*132=8448, 128*72=9216) */
#define K3_SMEM_FLOATS (64*QS3 + K3_U_FLOATS + 64*VS3 + 64*AS3 + 128 + 64)
#define K3_SMEM (K3_SMEM_FLOATS * sizeof(float))

__global__ __launch_bounds__(256)
void k_output(const float* __restrict__ qg_,
              const float* __restrict__ kg_,
              const float* __restrict__ vg_,
              float* __restrict__ outg) {
    extern __shared__ float sm[];
    float* qs    = sm;
    float* u     = qs + 64 * QS3;        // k~ then S0
    float* vs    = u + K3_U_FLOATS;
    float* As    = vs + 64 * VS3;
    float* ksum  = As + 64 * AS3;
    float* den   = ksum + 128;

    const int s = blockIdx.x >> 4;
    const int c = blockIdx.x & 15;
    const int t = threadIdx.x;

    // ---- Lookback: S0 register reduction over raw chunk partials i<c ----
    // Thread owns 8 float4 slots at f4 = j*256 + t (lane-contiguous loads).
    float4 s0acc[8];
#pragma unroll
    for (int j = 0; j < 8; j++) s0acc[j] = make_float4(0.f, 0.f, 0.f, 0.f);
    {
        const float4* kvb = reinterpret_cast<const float4*>(
            g_kv + (size_t)(s * NC) * D2 * DIM);
#pragma unroll 2
        for (int i = 0; i < c; i++) {
            const float4* p = kvb + (size_t)i * 2048 + t;
            float4 b[8];
#pragma unroll
            for (int j = 0; j < 8; j++) b[j] = __ldcg(p + j * 256);
#pragma unroll
            for (int j = 0; j < 8; j++) {
                s0acc[j].x += b[j].x; s0acc[j].y += b[j].y;
                s0acc[j].z += b[j].z; s0acc[j].w += b[j].w;
            }
        }
    }
    // ksum prefix (128 floats).
    if (t < D2) {
        float kacc = 0.f;
        const float* kb = g_ksum + (size_t)(s * NC) * D2 + t;
#pragma unroll 4
        for (int i = 0; i < c; i++) kacc += __ldcg(kb + i * D2);
        ksum[t] = kacc;
    }

    const float* qg = qg_ + (size_t)(s * LSEQ + c * CHK) * DIM;
    const float* kg = kg_ + (size_t)(s * LSEQ + c * CHK) * DIM;
    const float* vg = vg_ + (size_t)(s * LSEQ + c * CHK) * DIM;

#pragma unroll
    for (int i = t; i < CHK * DIM / 4; i += 256) {
        int j = i >> 4;
        int d = (i & 15) * 4;
        float4 q4 = reinterpret_cast<const float4*>(qg)[i];
        float4 k4 = reinterpret_cast<const float4*>(kg)[i];
        float4 v4 = reinterpret_cast<const float4*>(vg)[i];
        int gl = c * CHK + j;
        float w = 1.5707963267948966f * (float)(gl + 1) * (1.0f / (float)LSEQ);
        float sw, cw;
        __sincosf(w, &sw, &cw);
        float qx = fmaxf(q4.x, 0.f), qy = fmaxf(q4.y, 0.f);
        float qz = fmaxf(q4.z, 0.f), qw = fmaxf(q4.w, 0.f);
        float kx = fmaxf(k4.x, 0.f), ky = fmaxf(k4.y, 0.f);
        float kz = fmaxf(k4.z, 0.f), kw = fmaxf(k4.w, 0.f);
        *reinterpret_cast<float4*>(qs + j * QS3 + d) =
            make_float4(f2tf(qx * sw), f2tf(qy * sw), f2tf(qz * sw), f2tf(qw * sw));
        *reinterpret_cast<float4*>(qs + j * QS3 + 64 + d) =
            make_float4(f2tf(qx * cw), f2tf(qy * cw), f2tf(qz * cw), f2tf(qw * cw));
        *reinterpret_cast<float4*>(u + j * US3 + d) =
            make_float4(f2tf(kx * sw), f2tf(ky * sw), f2tf(kz * sw), f2tf(kw * sw));
        *reinterpret_cast<float4*>(u + j * US3 + 64 + d) =
            make_float4(f2tf(kx * cw), f2tf(ky * cw), f2tf(kz * cw), f2tf(kw * cw));
        *reinterpret_cast<float4*>(vs + j * VS3 + d) =
            make_float4(f2tf(v4.x), f2tf(v4.y), f2tf(v4.z), f2tf(v4.w));
    }
    __syncthreads();

    const int wid  = t >> 5;
    const int lane = t & 31;
    const int g    = lane >> 2;
    const int tig  = lane & 3;
    const int warpM = (wid >> 1) * 16;   // 0,16,32,48
    const int warpN = (wid & 1) * 32;    // 0,32

    // ---- Phase A: A = q~ @ k~^T, K=128 ----
    {
        float acc[4][4];
#pragma unroll
        for (int nt = 0; nt < 4; nt++)
#pragma unroll
            for (int cc = 0; cc < 4; cc++) acc[nt][cc] = 0.f;

#pragma unroll
        for (int kk = 0; kk < 16; kk++) {
            const int k0 = kk * 8;
            uint32_t af[4];
            af[0] = BITS(qs[(warpM + g)     * QS3 + k0 + tig]);
            af[1] = BITS(qs[(warpM + g + 8) * QS3 + k0 + tig]);
            af[2] = BITS(qs[(warpM + g)     * QS3 + k0 + tig + 4]);
            af[3] = BITS(qs[(warpM + g + 8) * QS3 + k0 + tig + 4]);
            uint32_t bf[4][2];
#pragma unroll
            for (int nt = 0; nt < 4; nt++) {
                int nb = warpN + nt * 8 + g;
                bf[nt][0] = BITS(u[nb * US3 + k0 + tig]);
                bf[nt][1] = BITS(u[nb * US3 + k0 + tig + 4]);
            }
#pragma unroll
            for (int nt = 0; nt < 4; nt++)
                mma_tf32(acc[nt], af, bf[nt], acc[nt]);
        }
#pragma unroll
        for (int nt = 0; nt < 4; nt++) {
#pragma unroll
            for (int cc = 0; cc < 4; cc++) {
                int l  = warpM + g + ((cc >= 2) ? 8 : 0);
                int jc = warpN + nt * 8 + 2 * tig + (cc & 1);
                As[l * AS3 + jc] = (jc <= l) ? f2tf(acc[nt][cc]) : 0.f;
            }
        }
    }
    __syncthreads();   // k~ region dead; As valid

    // ---- Write reduced S0 (tf32) into u [128][72] ----
#pragma unroll
    for (int j = 0; j < 8; j++) {
        int f4 = j * 256 + t;
        int r = f4 >> 4;
        int d = (f4 & 15) * 4;
        *reinterpret_cast<float4*>(u + r * S0S + d) =
            make_float4(f2tf(s0acc[j].x), f2tf(s0acc[j].y),
                        f2tf(s0acc[j].z), f2tf(s0acc[j].w));
    }

    // Denominators (uses qs, ksum, As).
    if (t < CHK) {
        int l = t;
        float d1 = 0.f;
#pragma unroll 8
        for (int kk = 0; kk < D2; kk++) d1 += qs[l * QS3 + kk] * ksum[kk];
        float d2v = 0.f;
        for (int jc = 0; jc <= l; jc++) d2v += As[l * AS3 + jc];
        den[l] = fmaxf(d1 + d2v, 1e-6f);
    }
    __syncthreads();

    // ---- Phase B: out = q~ @ S0 (K=128) + A @ v (K=64) ----
    float acc2[4][4];
#pragma unroll
    for (int nt = 0; nt < 4; nt++)
#pragma unroll
        for (int cc = 0; cc < 4; cc++) acc2[nt][cc] = 0.f;

#pragma unroll
    for (int kk = 0; kk < 16; kk++) {
        const int k0 = kk * 8;
        uint32_t af[4];
        af[0] = BITS(qs[(warpM + g)     * QS3 + k0 + tig]);
        af[1] = BITS(qs[(warpM + g + 8) * QS3 + k0 + tig]);
        af[2] = BITS(qs[(warpM + g)     * QS3 + k0 + tig + 4]);
        af[3] = BITS(qs[(warpM + g + 8) * QS3 + k0 + tig + 4]);
        uint32_t bf[4][2];
#pragma unroll
        for (int nt = 0; nt < 4; nt++) {
            int nb = warpN + nt * 8 + g;
            bf[nt][0] = BITS(u[(k0 + tig)     * S0S + nb]);
            bf[nt][1] = BITS(u[(k0 + tig + 4) * S0S + nb]);
        }
#pragma unroll
        for (int nt = 0; nt < 4; nt++)
            mma_tf32(acc2[nt], af, bf[nt], acc2[nt]);
    }
#pragma unroll
    for (int kk = 0; kk < 8; kk++) {
        const int k0 = kk * 8;
        uint32_t af[4];
        af[0] = BITS(As[(warpM + g)     * AS3 + k0 + tig]);
        af[1] = BITS(As[(warpM + g + 8) * AS3 + k0 + tig]);
        af[2] = BITS(As[(warpM + g)     * AS3 + k0 + tig + 4]);
        af[3] = BITS(As[(warpM + g + 8) * AS3 + k0 + tig + 4]);
        uint32_t bf[4][2];
#pragma unroll
        for (int nt = 0; nt < 4; nt++) {
            int nb = warpN + nt * 8 + g;
            bf[nt][0] = BITS(vs[(k0 + tig)     * VS3 + nb]);
            bf[nt][1] = BITS(vs[(k0 + tig + 4) * VS3 + nb]);
        }
#pragma unroll
        for (int nt = 0; nt < 4; nt++)
            mma_tf32(acc2[nt], af, bf[nt], acc2[nt]);
    }

    // Epilogue: divide by denom and store.
    float* outp = outg + (size_t)(s * LSEQ + c * CHK) * DIM;
    {
        int l0 = warpM + g;
        int l1 = l0 + 8;
        float inv0 = 1.0f / den[l0];
        float inv1 = 1.0f / den[l1];
#pragma unroll
        for (int nt = 0; nt < 4; nt++) {
            int n0 = warpN + nt * 8 + 2 * tig;
            *reinterpret_cast<float2*>(outp + l0 * DIM + n0) =
                make_float2(acc2[nt][0] * inv0, acc2[nt][1] * inv0);
            *reinterpret_cast<float2*>(outp + l1 * DIM + n0) =
                make_float2(acc2[nt][2] * inv1, acc2[nt][3] * inv1);
        }
    }
}

// ---------------------------------------------------------------------------
extern "C" void kernel_launch(void* const* d_in, const int* in_sizes, int n_in,
                              void* d_out, int out_size) {
    const float* q = (const float*)d_in[0];
    const float* k = (const float*)d_in[1];
    const float* v = (const float*)d_in[2];
    float* out = (float*)d_out;

    static bool attr_set = false;
    if (!attr_set) {
        cudaFuncSetAttribute(k_chunksum,
                             cudaFuncAttributeMaxDynamicSharedMemorySize, K1_SMEM);
        cudaFuncSetAttribute(k_output,
                             cudaFuncAttributeMaxDynamicSharedMemorySize, K3_SMEM);
        attr_set = true;
    }

    k_chunksum<<<NSEQ * NC, 256, K1_SMEM>>>(k, v);
    k_output<<<NSEQ * NC, 256, K3_SMEM>>>(q, k, v, out);
}

// round 13
// speedup vs baseline: 1.4306x; 1.4306x over previous
#include <cuda_runtime.h>
#include <math.h>
#include <stdint.h>

// Problem constants (B=1, H=16, L=1024, D=64)
#define NSEQ 16
#define LSEQ 1024
#define DIM  64
#define D2   128          // feature dim = 2*DIM
#define CHK  64           // chunk length
#define NC   (LSEQ/CHK)   // 16 chunks per sequence

// Scratch: per-(seq,chunk) KV sums [D2][DIM] and k-sums [D2] (prefix-scanned)
__device__ float g_kv[NSEQ * NC * D2 * DIM];    // 8 MB
__device__ float g_ksum[NSEQ * NC * D2];        // 128 KB

// ---------------------------------------------------------------------------
// helpers
// ---------------------------------------------------------------------------
__device__ __forceinline__ float f2tf(float x) {
    uint32_t r;
    asm("cvt.rna.tf32.f32 %0, %1;" : "=r"(r) : "f"(x));
    return __uint_as_float(r);
}

__device__ __forceinline__ void mma_tf32(float d[4],
                                         const uint32_t a[4],
                                         const uint32_t b[2],
                                         const float c[4]) {
    asm volatile(
        "mma.sync.aligned.m16n8k8.row.col.f32.tf32.tf32.f32 "
        "{%0,%1,%2,%3}, {%4,%5,%6,%7}, {%8,%9}, {%10,%11,%12,%13};\n"
        : "=f"(d[0]), "=f"(d[1]), "=f"(d[2]), "=f"(d[3])
        : "r"(a[0]), "r"(a[1]), "r"(a[2]), "r"(a[3]),
          "r"(b[0]), "r"(b[1]),
          "f"(c[0]), "f"(c[1]), "f"(c[2]), "f"(c[3]));
}

__device__ __forceinline__ void cpa16(uint32_t smem_dst, const void* gsrc) {
    asm volatile("cp.async.cg.shared.global [%0], [%1], 16;\n"
                 :: "r"(smem_dst), "l"(gsrc));
}
#define CPA_COMMIT() asm volatile("cp.async.commit_group;\n" ::: "memory")
#define CPA_WAIT0()  asm volatile("cp.async.wait_group 0;\n" ::: "memory")
#define CPA_WAIT1()  asm volatile("cp.async.wait_group 1;\n" ::: "memory")

#define BITS(x) __float_as_uint(x)

// ---------------------------------------------------------------------------
// Kernel 1: per-chunk KV sums via tensor cores.
// grid = 128 CTAs; CTA (s,pair) handles chunks 2*pair, 2*pair+1.
// Both chunks' raw k/v staged via cp.async at kernel start (full MLP).
// smem floats: raw0[8192], raw1[8192], ks[64][136], vs[64][72]
// ---------------------------------------------------------------------------
#define K1_KS 136
#define K1_VS 72
#define K1_RAW 8192                 /* rawk[4096] + rawv[4096] per chunk */
#define K1_SMEM_FLOATS (2*K1_RAW + CHK*K1_KS + CHK*K1_VS)
#define K1_SMEM (K1_SMEM_FLOATS * sizeof(float))

__global__ __launch_bounds__(256)
void k_chunksum(const float* __restrict__ kg_,
                const float* __restrict__ vg_) {
    extern __shared__ float sm[];
    float* raw0 = sm;                    // [8192]: k then v
    float* raw1 = sm + K1_RAW;
    float* ks   = sm + 2 * K1_RAW;       // [64][136]
    float* vs   = ks + CHK * K1_KS;      // [64][72]

    const int s    = blockIdx.x >> 3;
    const int pair = blockIdx.x & 7;
    const int c0   = 2 * pair;
    const int t    = threadIdx.x;

    const uint32_t smbase = (uint32_t)__cvta_generic_to_shared(sm);

    // Stage both chunks (k 16KB + v 16KB each) -- two commit groups.
#pragma unroll
    for (int cc = 0; cc < 2; cc++) {
        const float4* kg = reinterpret_cast<const float4*>(
            kg_ + (size_t)(s * LSEQ + (c0 + cc) * CHK) * DIM);
        const float4* vg = reinterpret_cast<const float4*>(
            vg_ + (size_t)(s * LSEQ + (c0 + cc) * CHK) * DIM);
        uint32_t rb = smbase + (cc * K1_RAW) * 4;
#pragma unroll
        for (int i = t; i < 1024; i += 256) {
            cpa16(rb + i * 16, kg + i);
            cpa16(rb + 4096 * 4 + i * 16, vg + i);
        }
        CPA_COMMIT();
    }

    const int wid  = t >> 5;
    const int lane = t & 31;
    const int g    = lane >> 2;
    const int tig  = lane & 3;
    const int warpM = (wid >> 1) * 32;   // 0,32,64,96 (d2)
    const int warpN = (wid & 1) * 32;    // 0,32 (dv)

#pragma unroll
    for (int cc = 0; cc < 2; cc++) {
        const int c = c0 + cc;
        float* raw = cc ? raw1 : raw0;
        if (cc == 0) { CPA_WAIT1(); } else { CPA_WAIT0(); }
        __syncthreads();

        // Feature-map from staging (smem) into ks/vs.
#pragma unroll
        for (int i = t; i < 1024; i += 256) {
            int j = i >> 4;
            int d = (i & 15) * 4;
            float4 k4 = *reinterpret_cast<float4*>(raw + i * 4);
            float4 v4 = *reinterpret_cast<float4*>(raw + 4096 + i * 4);
            int gl = c * CHK + j;
            float w = 1.5707963267948966f * (float)(gl + 1) * (1.0f / (float)LSEQ);
            float sw, cw;
            __sincosf(w, &sw, &cw);
            float kx = fmaxf(k4.x, 0.f), ky = fmaxf(k4.y, 0.f);
            float kz = fmaxf(k4.z, 0.f), kw = fmaxf(k4.w, 0.f);
            *reinterpret_cast<float4*>(ks + j * K1_KS + d) =
                make_float4(f2tf(kx * sw), f2tf(ky * sw), f2tf(kz * sw), f2tf(kw * sw));
            *reinterpret_cast<float4*>(ks + j * K1_KS + 64 + d) =
                make_float4(f2tf(kx * cw), f2tf(ky * cw), f2tf(kz * cw), f2tf(kw * cw));
            *reinterpret_cast<float4*>(vs + j * K1_VS + d) =
                make_float4(f2tf(v4.x), f2tf(v4.y), f2tf(v4.z), f2tf(v4.w));
        }
        __syncthreads();

        float acc[2][4][4];
#pragma unroll
        for (int mt = 0; mt < 2; mt++)
#pragma unroll
            for (int nt = 0; nt < 4; nt++)
#pragma unroll
                for (int q = 0; q < 4; q++) acc[mt][nt][q] = 0.f;

#pragma unroll
        for (int kk = 0; kk < 8; kk++) {
            const int k0 = kk * 8;
            uint32_t af[2][4];
#pragma unroll
            for (int mt = 0; mt < 2; mt++) {
                int mb = warpM + mt * 16 + g;
                af[mt][0] = BITS(ks[(k0 + tig)     * K1_KS + mb]);
                af[mt][1] = BITS(ks[(k0 + tig)     * K1_KS + mb + 8]);
                af[mt][2] = BITS(ks[(k0 + tig + 4) * K1_KS + mb]);
                af[mt][3] = BITS(ks[(k0 + tig + 4) * K1_KS + mb + 8]);
            }
            uint32_t bf[4][2];
#pragma unroll
            for (int nt = 0; nt < 4; nt++) {
                int nb = warpN + nt * 8 + g;
                bf[nt][0] = BITS(vs[(k0 + tig)     * K1_VS + nb]);
                bf[nt][1] = BITS(vs[(k0 + tig + 4) * K1_VS + nb]);
            }
#pragma unroll
            for (int mt = 0; mt < 2; mt++)
#pragma unroll
                for (int nt = 0; nt < 4; nt++)
                    mma_tf32(acc[mt][nt], af[mt], bf[nt], acc[mt][nt]);
        }

        // Store chunk KV sum (L2).
        float* outp = g_kv + (size_t)(s * NC + c) * D2 * DIM;
#pragma unroll
        for (int mt = 0; mt < 2; mt++)
#pragma unroll
            for (int nt = 0; nt < 4; nt++) {
                int m0 = warpM + mt * 16 + g;
                int n0 = warpN + nt * 8 + 2 * tig;
                __stcg((float2*)(outp + m0 * DIM + n0),
                       make_float2(acc[mt][nt][0], acc[mt][nt][1]));
                __stcg((float2*)(outp + (m0 + 8) * DIM + n0),
                       make_float2(acc[mt][nt][2], acc[mt][nt][3]));
            }

        // k-sum per feature dim.
        if (t < D2) {
            float ssum = 0.f;
#pragma unroll 8
            for (int j = 0; j < CHK; j++) ssum += ks[j * K1_KS + t];
            __stcg(&g_ksum[(size_t)(s * NC + c) * D2 + t], ssum);
        }
        __syncthreads();   // ks/vs reads done before next chunk overwrites
    }
}

// ---------------------------------------------------------------------------
// Kernel 2: exclusive prefix scan over chunks, MLP=16 preload.
// ---------------------------------------------------------------------------
__global__ __launch_bounds__(256)
void k_scan() {
    const int gtid = blockIdx.x * blockDim.x + threadIdx.x;
    if (gtid < NSEQ * 2048) {
        int s = gtid >> 11;
        int e = gtid & 2047;
        float4* base = reinterpret_cast<float4*>(g_kv) + (size_t)s * NC * 2048 + e;
        float4 tmp[NC];
#pragma unroll
        for (int c = 0; c < NC; c++) tmp[c] = base[(size_t)c * 2048];
        float4 run = make_float4(0.f, 0.f, 0.f, 0.f);
#pragma unroll
        for (int c = 0; c < NC; c++) {
            float4 x = tmp[c];
            base[(size_t)c * 2048] = run;
            run.x += x.x; run.y += x.y; run.z += x.z; run.w += x.w;
        }
    } else if (gtid < NSEQ * 2048 + NSEQ * D2) {
        int idx = gtid - NSEQ * 2048;
        int s = idx >> 7;
        int e = idx & 127;
        float* b2 = g_ksum + (size_t)s * NC * D2 + e;
        float tmp[NC];
#pragma unroll
        for (int c = 0; c < NC; c++) tmp[c] = b2[c * D2];
        float run = 0.f;
#pragma unroll
        for (int c = 0; c < NC; c++) {
            float x = tmp[c];
            b2[c * D2] = run;
            run += x;
        }
    }
}

// ---------------------------------------------------------------------------
// Kernel 3: per-chunk output. grid = 128 CTAs; CTA (s,pair) handles chunks
// 2*pair, 2*pair+1 with cp.async staged q/k/v and overlapped S0 prefetch.
// smem floats:
//   rawq[4096] rawk[4096] rawv[4096] qs[64][132] u[9216] vs[64][72]
//   As[64][68] ksum[128] den[64]
// ---------------------------------------------------------------------------
#define QS3 132
#define US3 132
#define S0S 72
#define VS3 72
#define AS3 68
#define K3_U_FLOATS 9216
#define K3_SMEM_FLOATS (3*4096 + 64*QS3 + K3_U_FLOATS + 64*VS3 + 64*AS3 + 128 + 64)
#define K3_SMEM (K3_SMEM_FLOATS * sizeof(float))

__global__ __launch_bounds__(256)
void k_output(const float* __restrict__ qg_,
              const float* __restrict__ kg_,
              const float* __restrict__ vg_,
              float* __restrict__ outg) {
    extern __shared__ float sm[];
    float* rawq = sm;
    float* rawk = rawq + 4096;
    float* rawv = rawk + 4096;
    float* qs   = rawv + 4096;
    float* u    = qs + 64 * QS3;        // k~ then S0
    float* vs   = u + K3_U_FLOATS;
    float* As   = vs + 64 * VS3;
    float* ksum = As + 64 * AS3;
    float* den  = ksum + 128;

    const int s    = blockIdx.x >> 3;
    const int pair = blockIdx.x & 7;
    const int c0   = 2 * pair;
    const int t    = threadIdx.x;

    const uint32_t smbase = (uint32_t)__cvta_generic_to_shared(sm);
    const uint32_t ubase  = (uint32_t)__cvta_generic_to_shared(u);

    // Stage chunk c0 q/k/v (48KB).
    {
        const float4* qg = reinterpret_cast<const float4*>(
            qg_ + (size_t)(s * LSEQ + c0 * CHK) * DIM);
        const float4* kg = reinterpret_cast<const float4*>(
            kg_ + (size_t)(s * LSEQ + c0 * CHK) * DIM);
        const float4* vg = reinterpret_cast<const float4*>(
            vg_ + (size_t)(s * LSEQ + c0 * CHK) * DIM);
#pragma unroll
        for (int i = t; i < 1024; i += 256) {
            cpa16(smbase + i * 16, qg + i);
            cpa16(smbase + 4096 * 4 + i * 16, kg + i);
            cpa16(smbase + 8192 * 4 + i * 16, vg + i);
        }
        CPA_COMMIT();
    }

    const int wid  = t >> 5;
    const int lane = t & 31;
    const int g    = lane >> 2;
    const int tig  = lane & 3;
    const int warpM = (wid >> 1) * 16;   // 0,16,32,48
    const int warpN = (wid & 1) * 32;    // 0,32

#pragma unroll
    for (int cc = 0; cc < 2; cc++) {
        const int c = c0 + cc;
        CPA_WAIT0();
        __syncthreads();

        // Feature-map from staging; ksum prefix load.
#pragma unroll
        for (int i = t; i < 1024; i += 256) {
            int j = i >> 4;
            int d = (i & 15) * 4;
            float4 q4 = *reinterpret_cast<float4*>(rawq + i * 4);
            float4 k4 = *reinterpret_cast<float4*>(rawk + i * 4);
            float4 v4 = *reinterpret_cast<float4*>(rawv + i * 4);
            int gl = c * CHK + j;
            float w = 1.5707963267948966f * (float)(gl + 1) * (1.0f / (float)LSEQ);
            float sw, cw;
            __sincosf(w, &sw, &cw);
            float qx = fmaxf(q4.x, 0.f), qy = fmaxf(q4.y, 0.f);
            float qz = fmaxf(q4.z, 0.f), qw = fmaxf(q4.w, 0.f);
            float kx = fmaxf(k4.x, 0.f), ky = fmaxf(k4.y, 0.f);
            float kz = fmaxf(k4.z, 0.f), kw = fmaxf(k4.w, 0.f);
            *reinterpret_cast<float4*>(qs + j * QS3 + d) =
                make_float4(f2tf(qx * sw), f2tf(qy * sw), f2tf(qz * sw), f2tf(qw * sw));
            *reinterpret_cast<float4*>(qs + j * QS3 + 64 + d) =
                make_float4(f2tf(qx * cw), f2tf(qy * cw), f2tf(qz * cw), f2tf(qw * cw));
            *reinterpret_cast<float4*>(u + j * US3 + d) =
                make_float4(f2tf(kx * sw), f2tf(ky * sw), f2tf(kz * sw), f2tf(kw * sw));
            *reinterpret_cast<float4*>(u + j * US3 + 64 + d) =
                make_float4(f2tf(kx * cw), f2tf(ky * cw), f2tf(kz * cw), f2tf(kw * cw));
            *reinterpret_cast<float4*>(vs + j * VS3 + d) =
                make_float4(f2tf(v4.x), f2tf(v4.y), f2tf(v4.z), f2tf(v4.w));
        }
        if (t < D2) ksum[t] = __ldcg(&g_ksum[(size_t)(s * NC + c) * D2 + t]);
        __syncthreads();

        // ---- Phase A: A = q~ @ k~^T, K=128 ----
        {
            float acc[4][4];
#pragma unroll
            for (int nt = 0; nt < 4; nt++)
#pragma unroll
                for (int q = 0; q < 4; q++) acc[nt][q] = 0.f;

#pragma unroll
            for (int kk = 0; kk < 16; kk++) {
                const int k0 = kk * 8;
                uint32_t af[4];
                af[0] = BITS(qs[(warpM + g)     * QS3 + k0 + tig]);
                af[1] = BITS(qs[(warpM + g + 8) * QS3 + k0 + tig]);
                af[2] = BITS(qs[(warpM + g)     * QS3 + k0 + tig + 4]);
                af[3] = BITS(qs[(warpM + g + 8) * QS3 + k0 + tig + 4]);
                uint32_t bf[4][2];
#pragma unroll
                for (int nt = 0; nt < 4; nt++) {
                    int nb = warpN + nt * 8 + g;
                    bf[nt][0] = BITS(u[nb * US3 + k0 + tig]);
                    bf[nt][1] = BITS(u[nb * US3 + k0 + tig + 4]);
                }
#pragma unroll
                for (int nt = 0; nt < 4; nt++)
                    mma_tf32(acc[nt], af, bf[nt], acc[nt]);
            }
#pragma unroll
            for (int nt = 0; nt < 4; nt++) {
#pragma unroll
                for (int q = 0; q < 4; q++) {
                    int l  = warpM + g + ((q >= 2) ? 8 : 0);
                    int jc = warpN + nt * 8 + 2 * tig + (q & 1);
                    As[l * AS3 + jc] = (jc <= l) ? f2tf(acc[nt][q]) : 0.f;
                }
            }
        }
        __syncthreads();   // u (k~) reads done; As valid

        // ---- Prefetch S0 into u; then stage next chunk (cc==0). ----
        {
            const float4* kvg = reinterpret_cast<const float4*>(
                g_kv + (size_t)(s * NC + c) * D2 * DIM);
#pragma unroll
            for (int i = t; i < 2048; i += 256) {
                int r = i >> 4;
                int d = (i & 15) * 4;
                cpa16(ubase + (r * S0S + d) * 4, kvg + i);
            }
            CPA_COMMIT();
        }
        if (cc == 0) {
            const float4* qg = reinterpret_cast<const float4*>(
                qg_ + (size_t)(s * LSEQ + (c0 + 1) * CHK) * DIM);
            const float4* kg = reinterpret_cast<const float4*>(
                kg_ + (size_t)(s * LSEQ + (c0 + 1) * CHK) * DIM);
            const float4* vg = reinterpret_cast<const float4*>(
                vg_ + (size_t)(s * LSEQ + (c0 + 1) * CHK) * DIM);
#pragma unroll
            for (int i = t; i < 1024; i += 256) {
                cpa16(smbase + i * 16, qg + i);
                cpa16(smbase + 4096 * 4 + i * 16, kg + i);
                cpa16(smbase + 8192 * 4 + i * 16, vg + i);
            }
            CPA_COMMIT();
        }

        // Denominators (qs, ksum, As -- disjoint from in-flight copies).
        if (t < CHK) {
            int l = t;
            float d1 = 0.f;
#pragma unroll 8
            for (int kk = 0; kk < D2; kk++) d1 += qs[l * QS3 + kk] * ksum[kk];
            float d2v = 0.f;
            for (int jc = 0; jc <= l; jc++) d2v += As[l * AS3 + jc];
            den[l] = fmaxf(d1 + d2v, 1e-6f);
        }
        if (cc == 0) { CPA_WAIT1(); } else { CPA_WAIT0(); }  // S0 arrived
        __syncthreads();

        // ---- Phase B: out = q~ @ S0 (K=128) + A @ v (K=64) ----
        float acc2[4][4];
#pragma unroll
        for (int nt = 0; nt < 4; nt++)
#pragma unroll
            for (int q = 0; q < 4; q++) acc2[nt][q] = 0.f;

#pragma unroll
        for (int kk = 0; kk < 16; kk++) {
            const int k0 = kk * 8;
            uint32_t af[4];
            af[0] = BITS(qs[(warpM + g)     * QS3 + k0 + tig]);
            af[1] = BITS(qs[(warpM + g + 8) * QS3 + k0 + tig]);
            af[2] = BITS(qs[(warpM + g)     * QS3 + k0 + tig + 4]);
            af[3] = BITS(qs[(warpM + g + 8) * QS3 + k0 + tig + 4]);
            uint32_t bf[4][2];
#pragma unroll
            for (int nt = 0; nt < 4; nt++) {
                int nb = warpN + nt * 8 + g;
                bf[nt][0] = BITS(u[(k0 + tig)     * S0S + nb]);
                bf[nt][1] = BITS(u[(k0 + tig + 4) * S0S + nb]);
            }
#pragma unroll
            for (int nt = 0; nt < 4; nt++)
                mma_tf32(acc2[nt], af, bf[nt], acc2[nt]);
        }
#pragma unroll
        for (int kk = 0; kk < 8; kk++) {
            const int k0 = kk * 8;
            uint32_t af[4];
            af[0] = BITS(As[(warpM + g)     * AS3 + k0 + tig]);
            af[1] = BITS(As[(warpM + g + 8) * AS3 + k0 + tig]);
            af[2] = BITS(As[(warpM + g)     * AS3 + k0 + tig + 4]);
            af[3] = BITS(As[(warpM + g + 8) * AS3 + k0 + tig + 4]);
            uint32_t bf[4][2];
#pragma unroll
            for (int nt = 0; nt < 4; nt++) {
                int nb = warpN + nt * 8 + g;
                bf[nt][0] = BITS(vs[(k0 + tig)     * VS3 + nb]);
                bf[nt][1] = BITS(vs[(k0 + tig + 4) * VS3 + nb]);
            }
#pragma unroll
            for (int nt = 0; nt < 4; nt++)
                mma_tf32(acc2[nt], af, bf[nt], acc2[nt]);
        }

        // Epilogue.
        float* outp = outg + (size_t)(s * LSEQ + c * CHK) * DIM;
        {
            int l0 = warpM + g;
            int l1 = l0 + 8;
            float inv0 = 1.0f / den[l0];
            float inv1 = 1.0f / den[l1];
#pragma unroll
            for (int nt = 0; nt < 4; nt++) {
                int n0 = warpN + nt * 8 + 2 * tig;
                *reinterpret_cast<float2*>(outp + l0 * DIM + n0) =
                    make_float2(acc2[nt][0] * inv0, acc2[nt][1] * inv0);
                *reinterpret_cast<float2*>(outp + l1 * DIM + n0) =
                    make_float2(acc2[nt][2] * inv1, acc2[nt][3] * inv1);
            }
        }
        __syncthreads();   // all smem reads done before next iteration
    }
}

// ---------------------------------------------------------------------------
extern "C" void kernel_launch(void* const* d_in, const int* in_sizes, int n_in,
                              void* d_out, int out_size) {
    const float* q = (const float*)d_in[0];
    const float* k = (const float*)d_in[1];
    const float* v = (const float*)d_in[2];
    float* out = (float*)d_out;

    static bool attr_set = false;
    if (!attr_set) {
        cudaFuncSetAttribute(k_chunksum,
                             cudaFuncAttributeMaxDynamicSharedMemorySize, K1_SMEM);
        cudaFuncSetAttribute(k_output,
                             cudaFuncAttributeMaxDynamicSharedMemorySize, K3_SMEM);
        attr_set = true;
    }

    k_chunksum<<<128, 256, K1_SMEM>>>(k, v);
    int scan_threads = NSEQ * 2048 + NSEQ * D2;            // 34816
    k_scan<<<(scan_threads + 255) / 256, 256>>>();
    k_output<<<128, 256, K3_SMEM>>>(q, k, v, out);
}

// round 17
// speedup vs baseline: 1.5172x; 1.0605x over previous
#include <cuda_runtime.h>
#include <math.h>
#include <stdint.h>

// Problem constants (B=1, H=16, L=1024, D=64)
#define NSEQ 16
#define LSEQ 1024
#define DIM  64
#define D2   128          // feature dim = 2*DIM
#define CHK  64           // chunk length
#define NC   (LSEQ/CHK)   // 16 chunks per sequence

// Scratch: per-(seq,chunk) KV sums [D2][DIM] and k-sums [D2] (prefix-scanned)
__device__ float g_kv[NSEQ * NC * D2 * DIM];    // 8 MB
__device__ float g_ksum[NSEQ * NC * D2];        // 128 KB

// ---------------------------------------------------------------------------
// helpers
// ---------------------------------------------------------------------------
__device__ __forceinline__ float f2tf(float x) {
    uint32_t r;
    asm("cvt.rna.tf32.f32 %0, %1;" : "=r"(r) : "f"(x));
    return __uint_as_float(r);
}

__device__ __forceinline__ void mma_tf32(float d[4],
                                         const uint32_t a[4],
                                         const uint32_t b[2],
                                         const float c[4]) {
    asm volatile(
        "mma.sync.aligned.m16n8k8.row.col.f32.tf32.tf32.f32 "
        "{%0,%1,%2,%3}, {%4,%5,%6,%7}, {%8,%9}, {%10,%11,%12,%13};\n"
        : "=f"(d[0]), "=f"(d[1]), "=f"(d[2]), "=f"(d[3])
        : "r"(a[0]), "r"(a[1]), "r"(a[2]), "r"(a[3]),
          "r"(b[0]), "r"(b[1]),
          "f"(c[0]), "f"(c[1]), "f"(c[2]), "f"(c[3]));
}

__device__ __forceinline__ void cpa16(uint32_t smem_dst, const void* gsrc) {
    asm volatile("cp.async.cg.shared.global [%0], [%1], 16;\n"
                 :: "r"(smem_dst), "l"(gsrc));
}

#define BITS(x) __float_as_uint(x)

// ---------------------------------------------------------------------------
// Kernel 1: per-chunk KV sums via tensor cores.
// grid = NSEQ*NC = 256, 256 threads (8 warps).
// C[128(d2) x 64(dv)] = k~^T @ v over K=64 positions.
// ---------------------------------------------------------------------------
#define K1_KS 136
#define K1_VS 72
#define K1_SMEM ((CHK*K1_KS + CHK*K1_VS) * sizeof(float))

__global__ __launch_bounds__(256)
void k_chunksum(const float* __restrict__ kg_,
                const float* __restrict__ vg_) {
    extern __shared__ float sm[];
    float* ks = sm;                   // [64][136]
    float* vs = sm + CHK * K1_KS;     // [64][72]

    const int s = blockIdx.x >> 4;
    const int c = blockIdx.x & 15;
    const int t = threadIdx.x;

    const float* kg = kg_ + (size_t)(s * LSEQ + c * CHK) * DIM;
    const float* vg = vg_ + (size_t)(s * LSEQ + c * CHK) * DIM;

#pragma unroll
    for (int i = t; i < CHK * DIM / 4; i += 256) {
        int j = i >> 4;
        int d = (i & 15) * 4;
        float4 k4 = reinterpret_cast<const float4*>(kg)[i];
        float4 v4 = reinterpret_cast<const float4*>(vg)[i];
        int gl = c * CHK + j;
        float w = 1.5707963267948966f * (float)(gl + 1) * (1.0f / (float)LSEQ);
        float sw, cw;
        __sincosf(w, &sw, &cw);
        float kx = fmaxf(k4.x, 0.f), ky = fmaxf(k4.y, 0.f);
        float kz = fmaxf(k4.z, 0.f), kw = fmaxf(k4.w, 0.f);
        *reinterpret_cast<float4*>(ks + j * K1_KS + d) =
            make_float4(f2tf(kx * sw), f2tf(ky * sw), f2tf(kz * sw), f2tf(kw * sw));
        *reinterpret_cast<float4*>(ks + j * K1_KS + 64 + d) =
            make_float4(f2tf(kx * cw), f2tf(ky * cw), f2tf(kz * cw), f2tf(kw * cw));
        *reinterpret_cast<float4*>(vs + j * K1_VS + d) =
            make_float4(f2tf(v4.x), f2tf(v4.y), f2tf(v4.z), f2tf(v4.w));
    }
    __syncthreads();

    const int wid  = t >> 5;
    const int lane = t & 31;
    const int g    = lane >> 2;
    const int tig  = lane & 3;
    const int warpM = (wid >> 1) * 32;   // 0,32,64,96 (d2)
    const int warpN = (wid & 1) * 32;    // 0,32 (dv)

    float acc[2][4][4];
#pragma unroll
    for (int mt = 0; mt < 2; mt++)
#pragma unroll
        for (int nt = 0; nt < 4; nt++)
#pragma unroll
            for (int cc = 0; cc < 4; cc++) acc[mt][nt][cc] = 0.f;

#pragma unroll
    for (int kk = 0; kk < 8; kk++) {
        const int k0 = kk * 8;
        uint32_t af[2][4];
#pragma unroll
        for (int mt = 0; mt < 2; mt++) {
            int mb = warpM + mt * 16 + g;
            af[mt][0] = BITS(ks[(k0 + tig)     * K1_KS + mb]);
            af[mt][1] = BITS(ks[(k0 + tig)     * K1_KS + mb + 8]);
            af[mt][2] = BITS(ks[(k0 + tig + 4) * K1_KS + mb]);
            af[mt][3] = BITS(ks[(k0 + tig + 4) * K1_KS + mb + 8]);
        }
        uint32_t bf[4][2];
#pragma unroll
        for (int nt = 0; nt < 4; nt++) {
            int nb = warpN + nt * 8 + g;
            bf[nt][0] = BITS(vs[(k0 + tig)     * K1_VS + nb]);
            bf[nt][1] = BITS(vs[(k0 + tig + 4) * K1_VS + nb]);
        }
#pragma unroll
        for (int mt = 0; mt < 2; mt++)
#pragma unroll
            for (int nt = 0; nt < 4; nt++)
                mma_tf32(acc[mt][nt], af[mt], bf[nt], acc[mt][nt]);
    }

    // Store chunk KV sum.
    float* outp = g_kv + (size_t)(s * NC + c) * D2 * DIM;
#pragma unroll
    for (int mt = 0; mt < 2; mt++)
#pragma unroll
        for (int nt = 0; nt < 4; nt++) {
            int m0 = warpM + mt * 16 + g;
            int n0 = warpN + nt * 8 + 2 * tig;
            __stcg((float2*)(outp + m0 * DIM + n0),
                   make_float2(acc[mt][nt][0], acc[mt][nt][1]));
            __stcg((float2*)(outp + (m0 + 8) * DIM + n0),
                   make_float2(acc[mt][nt][2], acc[mt][nt][3]));
        }

    // k-sum per feature dim (4 parallel accumulator chains).
    if (t < D2) {
        float a0 = 0.f, a1 = 0.f, a2 = 0.f, a3 = 0.f;
#pragma unroll
        for (int j = 0; j < CHK; j += 4) {
            a0 += ks[(j + 0) * K1_KS + t];
            a1 += ks[(j + 1) * K1_KS + t];
            a2 += ks[(j + 2) * K1_KS + t];
            a3 += ks[(j + 3) * K1_KS + t];
        }
        __stcg(&g_ksum[(size_t)(s * NC + c) * D2 + t], (a0 + a1) + (a2 + a3));
    }
}

// ---------------------------------------------------------------------------
// Kernel 2: exclusive prefix scan over chunks. MLP=16 preload.
// threads: 32768 (kv float4 cols) + 2048 (ksum cols) = 34816
// ---------------------------------------------------------------------------
__global__ __launch_bounds__(256)
void k_scan() {
    const int gtid = blockIdx.x * blockDim.x + threadIdx.x;
    if (gtid < NSEQ * 2048) {
        int s = gtid >> 11;
        int e = gtid & 2047;
        float4* base = reinterpret_cast<float4*>(g_kv) + (size_t)s * NC * 2048 + e;
        float4 tmp[NC];
#pragma unroll
        for (int c = 0; c < NC; c++) tmp[c] = base[(size_t)c * 2048];
        float4 run = make_float4(0.f, 0.f, 0.f, 0.f);
#pragma unroll
        for (int c = 0; c < NC; c++) {
            float4 x = tmp[c];
            base[(size_t)c * 2048] = run;
            run.x += x.x; run.y += x.y; run.z += x.z; run.w += x.w;
        }
    } else if (gtid < NSEQ * 2048 + NSEQ * D2) {
        int idx = gtid - NSEQ * 2048;
        int s = idx >> 7;
        int e = idx & 127;
        float* b2 = g_ksum + (size_t)s * NC * D2 + e;
        float tmp[NC];
#pragma unroll
        for (int c = 0; c < NC; c++) tmp[c] = b2[c * D2];
        float run = 0.f;
#pragma unroll
        for (int c = 0; c < NC; c++) {
            float x = tmp[c];
            b2[c * D2] = run;
            run += x;
        }
    }
}

// ---------------------------------------------------------------------------
// Kernel 3: per-chunk output. grid = NSEQ*NC, 256 threads.
// S0 has a DEDICATED smem region; its cp.async is issued FIRST so the copy
// overlaps the entire load + feature-map + phase-A stretch.
// smem floats:
//   qs[64][132]  kt[64][132]  s0[128][72]  vs[64][72]  As[64][68]
//   ksum[128]  den[64]                                -> 35264 floats (138 KB)
// ---------------------------------------------------------------------------
#define QS3 132
#define KT3 132
#define S0S 72
#define VS3 72
#define AS3 68
#define K3_SMEM_FLOATS (64*QS3 + 64*KT3 + 128*S0S + 64*VS3 + 64*AS3 + 128 + 64)
#define K3_SMEM (K3_SMEM_FLOATS * sizeof(float))

__global__ __launch_bounds__(256)
void k_output(const float* __restrict__ qg_,
              const float* __restrict__ kg_,
              const float* __restrict__ vg_,
              float* __restrict__ outg) {
    extern __shared__ float sm[];
    float* qs   = sm;
    float* kt   = qs + 64 * QS3;
    float* s0   = kt + 64 * KT3;
    float* vs   = s0 + 128 * S0S;
    float* As   = vs + 64 * VS3;
    float* ksum = As + 64 * AS3;
    float* den  = ksum + 128;

    const int s = blockIdx.x >> 4;
    const int c = blockIdx.x & 15;
    const int t = threadIdx.x;

    // ---- 1. Issue S0 prefetch FIRST (overlaps everything up to phase B) ----
    {
        const float4* kvg = reinterpret_cast<const float4*>(
            g_kv + (size_t)(s * NC + c) * D2 * DIM);
        uint32_t s0base = (uint32_t)__cvta_generic_to_shared(s0);
#pragma unroll
        for (int i = t; i < D2 * DIM / 4; i += 256) {
            int r = i >> 4;
            int d = (i & 15) * 4;
            cpa16(s0base + (r * S0S + d) * 4, kvg + i);
        }
        asm volatile("cp.async.commit_group;\n" ::: "memory");
    }

    // ---- 2. Load + feature-map q/k/v ----
    const float* qg = qg_ + (size_t)(s * LSEQ + c * CHK) * DIM;
    const float* kg = kg_ + (size_t)(s * LSEQ + c * CHK) * DIM;
    const float* vg = vg_ + (size_t)(s * LSEQ + c * CHK) * DIM;

#pragma unroll
    for (int i = t; i < CHK * DIM / 4; i += 256) {
        int j = i >> 4;
        int d = (i & 15) * 4;
        float4 q4 = reinterpret_cast<const float4*>(qg)[i];
        float4 k4 = reinterpret_cast<const float4*>(kg)[i];
        float4 v4 = reinterpret_cast<const float4*>(vg)[i];
        int gl = c * CHK + j;
        float w = 1.5707963267948966f * (float)(gl + 1) * (1.0f / (float)LSEQ);
        float sw, cw;
        __sincosf(w, &sw, &cw);
        float qx = fmaxf(q4.x, 0.f), qy = fmaxf(q4.y, 0.f);
        float qz = fmaxf(q4.z, 0.f), qw = fmaxf(q4.w, 0.f);
        float kx = fmaxf(k4.x, 0.f), ky = fmaxf(k4.y, 0.f);
        float kz = fmaxf(k4.z, 0.f), kw = fmaxf(k4.w, 0.f);
        *reinterpret_cast<float4*>(qs + j * QS3 + d) =
            make_float4(f2tf(qx * sw), f2tf(qy * sw), f2tf(qz * sw), f2tf(qw * sw));
        *reinterpret_cast<float4*>(qs + j * QS3 + 64 + d) =
            make_float4(f2tf(qx * cw), f2tf(qy * cw), f2tf(qz * cw), f2tf(qw * cw));
        *reinterpret_cast<float4*>(kt + j * KT3 + d) =
            make_float4(f2tf(kx * sw), f2tf(ky * sw), f2tf(kz * sw), f2tf(kw * sw));
        *reinterpret_cast<float4*>(kt + j * KT3 + 64 + d) =
            make_float4(f2tf(kx * cw), f2tf(ky * cw), f2tf(kz * cw), f2tf(kw * cw));
        *reinterpret_cast<float4*>(vs + j * VS3 + d) =
            make_float4(f2tf(v4.x), f2tf(v4.y), f2tf(v4.z), f2tf(v4.w));
    }
    if (t < D2) ksum[t] = g_ksum[(size_t)(s * NC + c) * D2 + t];
    __syncthreads();

    const int wid  = t >> 5;
    const int lane = t & 31;
    const int g    = lane >> 2;
    const int tig  = lane & 3;
    const int warpM = (wid >> 1) * 16;   // 0,16,32,48
    const int warpN = (wid & 1) * 32;    // 0,32

    // ---- 3. Phase A: A = q~ @ k~^T, K=128 ----
    {
        float acc[4][4];
#pragma unroll
        for (int nt = 0; nt < 4; nt++)
#pragma unroll
            for (int cc = 0; cc < 4; cc++) acc[nt][cc] = 0.f;

#pragma unroll
        for (int kk = 0; kk < 16; kk++) {
            const int k0 = kk * 8;
            uint32_t af[4];
            af[0] = BITS(qs[(warpM + g)     * QS3 + k0 + tig]);
            af[1] = BITS(qs[(warpM + g + 8) * QS3 + k0 + tig]);
            af[2] = BITS(qs[(warpM + g)     * QS3 + k0 + tig + 4]);
            af[3] = BITS(qs[(warpM + g + 8) * QS3 + k0 + tig + 4]);
            uint32_t bf[4][2];
#pragma unroll
            for (int nt = 0; nt < 4; nt++) {
                int nb = warpN + nt * 8 + g;
                bf[nt][0] = BITS(kt[nb * KT3 + k0 + tig]);
                bf[nt][1] = BITS(kt[nb * KT3 + k0 + tig + 4]);
            }
#pragma unroll
            for (int nt = 0; nt < 4; nt++)
                mma_tf32(acc[nt], af, bf[nt], acc[nt]);
        }
#pragma unroll
        for (int nt = 0; nt < 4; nt++) {
#pragma unroll
            for (int cc = 0; cc < 4; cc++) {
                int l  = warpM + g + ((cc >= 2) ? 8 : 0);
                int jc = warpN + nt * 8 + 2 * tig + (cc & 1);
                As[l * AS3 + jc] = (jc <= l) ? f2tf(acc[nt][cc]) : 0.f;
            }
        }
    }
    __syncthreads();   // As valid

    // ---- 4. Denominators (parallel chains; masked As entries are 0) ----
    if (t < CHK) {
        int l = t;
        float a0 = 0.f, a1 = 0.f, a2 = 0.f, a3 = 0.f;
#pragma unroll
        for (int kk = 0; kk < D2; kk += 4) {
            a0 += qs[l * QS3 + kk + 0] * ksum[kk + 0];
            a1 += qs[l * QS3 + kk + 1] * ksum[kk + 1];
            a2 += qs[l * QS3 + kk + 2] * ksum[kk + 2];
            a3 += qs[l * QS3 + kk + 3] * ksum[kk + 3];
        }
        float b0 = 0.f, b1 = 0.f, b2 = 0.f, b3 = 0.f;
#pragma unroll
        for (int jc = 0; jc < CHK; jc += 4) {
            b0 += As[l * AS3 + jc + 0];
            b1 += As[l * AS3 + jc + 1];
            b2 += As[l * AS3 + jc + 2];
            b3 += As[l * AS3 + jc + 3];
        }
        den[l] = fmaxf(((a0 + a1) + (a2 + a3)) + ((b0 + b1) + (b2 + b3)), 1e-6f);
    }

    // ---- 5. S0 has landed long ago; tf32-round in place ----
    asm volatile("cp.async.wait_group 0;\n" ::: "memory");
    __syncthreads();
#pragma unroll
    for (int i = t; i < D2 * DIM / 4; i += 256) {
        int r = i >> 4;
        int d = (i & 15) * 4;
        float4* p = reinterpret_cast<float4*>(s0 + r * S0S + d);
        float4 x = *p;
        *p = make_float4(f2tf(x.x), f2tf(x.y), f2tf(x.z), f2tf(x.w));
    }
    __syncthreads();

    // ---- 6. Phase B: out = q~ @ S0 (K=128) + A @ v (K=64) ----
    float acc2[4][4];
#pragma unroll
    for (int nt = 0; nt < 4; nt++)
#pragma unroll
        for (int cc = 0; cc < 4; cc++) acc2[nt][cc] = 0.f;

#pragma unroll
    for (int kk = 0; kk < 16; kk++) {
        const int k0 = kk * 8;
        uint32_t af[4];
        af[0] = BITS(qs[(warpM + g)     * QS3 + k0 + tig]);
        af[1] = BITS(qs[(warpM + g + 8) * QS3 + k0 + tig]);
        af[2] = BITS(qs[(warpM + g)     * QS3 + k0 + tig + 4]);
        af[3] = BITS(qs[(warpM + g + 8) * QS3 + k0 + tig + 4]);
        uint32_t bf[4][2];
#pragma unroll
        for (int nt = 0; nt < 4; nt++) {
            int nb = warpN + nt * 8 + g;
            bf[nt][0] = BITS(s0[(k0 + tig)     * S0S + nb]);
            bf[nt][1] = BITS(s0[(k0 + tig + 4) * S0S + nb]);
        }
#pragma unroll
        for (int nt = 0; nt < 4; nt++)
            mma_tf32(acc2[nt], af, bf[nt], acc2[nt]);
    }
#pragma unroll
    for (int kk = 0; kk < 8; kk++) {
        const int k0 = kk * 8;
        uint32_t af[4];
        af[0] = BITS(As[(warpM + g)     * AS3 + k0 + tig]);
        af[1] = BITS(As[(warpM + g + 8) * AS3 + k0 + tig]);
        af[2] = BITS(As[(warpM + g)     * AS3 + k0 + tig + 4]);
        af[3] = BITS(As[(warpM + g + 8) * AS3 + k0 + tig + 4]);
        uint32_t bf[4][2];
#pragma unroll
        for (int nt = 0; nt < 4; nt++) {
            int nb = warpN + nt * 8 + g;
            bf[nt][0] = BITS(vs[(k0 + tig)     * VS3 + nb]);
            bf[nt][1] = BITS(vs[(k0 + tig + 4) * VS3 + nb]);
        }
#pragma unroll
        for (int nt = 0; nt < 4; nt++)
            mma_tf32(acc2[nt], af, bf[nt], acc2[nt]);
    }

    // ---- 7. Epilogue ----
    float* outp = outg + (size_t)(s * LSEQ + c * CHK) * DIM;
    {
        int l0 = warpM + g;
        int l1 = l0 + 8;
        float inv0 = 1.0f / den[l0];
        float inv1 = 1.0f / den[l1];
#pragma unroll
        for (int nt = 0; nt < 4; nt++) {
            int n0 = warpN + nt * 8 + 2 * tig;
            *reinterpret_cast<float2*>(outp + l0 * DIM + n0) =
                make_float2(acc2[nt][0] * inv0, acc2[nt][1] * inv0);
            *reinterpret_cast<float2*>(outp + l1 * DIM + n0) =
                make_float2(acc2[nt][2] * inv1, acc2[nt][3] * inv1);
        }
    }
}

// ---------------------------------------------------------------------------
extern "C" void kernel_launch(void* const* d_in, const int* in_sizes, int n_in,
                              void* d_out, int out_size) {
    const float* q = (const float*)d_in[0];
    const float* k = (const float*)d_in[1];
    const float* v = (const float*)d_in[2];
    float* out = (float*)d_out;

    static bool attr_set = false;
    if (!attr_set) {
        cudaFuncSetAttribute(k_chunksum,
                             cudaFuncAttributeMaxDynamicSharedMemorySize, K1_SMEM);
        cudaFuncSetAttribute(k_output,
                             cudaFuncAttributeMaxDynamicSharedMemorySize, K3_SMEM);
        attr_set = true;
    }

    k_chunksum<<<NSEQ * NC, 256, K1_SMEM>>>(k, v);
    int scan_threads = NSEQ * 2048 + NSEQ * D2;            // 34816
    k_scan<<<(scan_threads + 255) / 256, 256>>>();
    k_output<<<NSEQ * NC, 256, K3_SMEM>>>(q, k, v, out);
}